// round 7
// baseline (speedup 1.0000x reference)
#include <cuda_runtime.h>
#include <cstdint>

// ---------------------------------------------------------------------------
// MVGeometricBilinear: PGA G(3,0,1) geometric product + equivariant join.
//   out[..., 0:16]  = x * y          (geometric product, e0^2 = 0)
//   out[..., 16:32] = ref_e0123 * dual(dual(x) ^ dual(y))
//
// Round 7 (resubmit of round 5; round-6 bench died to container infra):
// double-buffered cp.async (LDGSTS) grid-stride pipeline so every block keeps
// an input-tile prefetch in flight while computing the current tile.
// Compute core unchanged from the validated round-3/4 kernels.
// ---------------------------------------------------------------------------

// Basis order (grade-sorted, matching the reference):
// 0:1  1:e0 2:e1 3:e2 4:e3  5:e01 6:e02 7:e03 8:e12 9:e13 10:e23
// 11:e012 12:e013 13:e023 14:e123 15:e0123
__host__ __device__ constexpr int maskOf(int i) {
    constexpr int m[16] = {0, 1, 2, 4, 8, 3, 5, 9, 6, 10, 12, 7, 11, 13, 14, 15};
    return m[i];
}
__host__ __device__ constexpr int idxOfMask(int m) {
    constexpr int t[16] = {0, 1, 2, 5, 3, 6, 8, 11, 4, 7, 9, 12, 10, 13, 14, 15};
    return t[m];
}
__host__ __device__ constexpr int reorderSign(int a, int b) {
    int s = 0;
    for (int j = 0; j < 4; j++)
        if (b & (1 << j))
            for (int i = j + 1; i < 4; i++)
                if (a & (1 << i)) s++;
    return (s & 1) ? -1 : 1;
}
__host__ __device__ constexpr int gpSign(int i, int j) {
    const int a = maskOf(i), b = maskOf(j);
    if (a & b & 1) return 0;              // shared degenerate e0 -> vanishes
    return reorderSign(a, b);
}
__host__ __device__ constexpr int gpIdx(int i, int j) {
    return idxOfMask(maskOf(i) ^ maskOf(j));
}
__host__ __device__ constexpr int cIdx(int i) { return idxOfMask(15 ^ maskOf(i)); }
__host__ __device__ constexpr int cSign(int i) { return reorderSign(maskOf(i), 15 ^ maskOf(i)); }
__host__ __device__ constexpr int jSign(int i, int j) {
    const int a = maskOf(cIdx(i)), b = maskOf(cIdx(j));
    if (a & b) return 0;
    const int m = idxOfMask(a | b);
    return reorderSign(a, b) * cSign(i) * cSign(j) * cSign(m);
}
__host__ __device__ constexpr int jIdx(int i, int j) {
    const int a = maskOf(cIdx(i)), b = maskOf(cIdx(j));
    if (a & b) return 0;
    return cIdx(idxOfMask(a | b));
}

// ---------------------------------------------------------------------------

constexpr int TPB  = 128;   // threads per block
constexpr int TILE = 128;   // points per tile (== TPB)
constexpr int SXW  = 20;    // smem stride (floats) per point, inputs (16+4 pad)
constexpr int SOW  = 36;    // smem stride (floats) per point, outputs (32+4 pad)
constexpr int BUFF = TILE * SXW * 2;   // floats per input buffer (x + y) = 5120

__device__ __forceinline__ uint32_t smem_u32(const void* p) {
    return (uint32_t)__cvta_generic_to_shared(p);
}
__device__ __forceinline__ void cp16(uint32_t dst, const void* src) {
    asm volatile("cp.async.cg.shared.global [%0], [%1], 16;\n" :: "r"(dst), "l"(src));
}
__device__ __forceinline__ void cp_commit() {
    asm volatile("cp.async.commit_group;\n" ::: "memory");
}
template <int N> __device__ __forceinline__ void cp_wait() {
    asm volatile("cp.async.wait_group %0;\n" :: "n"(N) : "memory");
}

// Compute core: 16x16 compile-time-signed bilinear (validated rounds 3-5).
__device__ __forceinline__ void mv_compute(const float x[16], const float y[16],
                                           float r, float gp[16], float jn[16])
{
#pragma unroll
    for (int k = 0; k < 16; k++) { gp[k] = 0.0f; jn[k] = 0.0f; }
#pragma unroll
    for (int i = 0; i < 16; i++) {
#pragma unroll
        for (int j = 0; j < 16; j++) {
            {
                const int s = gpSign(i, j);
                const int k = gpIdx(i, j);
                if (s == 1)       gp[k] += x[i] * y[j];
                else if (s == -1) gp[k] -= x[i] * y[j];
            }
            {
                const int s = jSign(i, j);
                const int k = jIdx(i, j);
                if (s == 1)       jn[k] += x[i] * y[j];
                else if (s == -1) jn[k] -= x[i] * y[j];
            }
        }
    }
#pragma unroll
    for (int k = 0; k < 16; k++) jn[k] *= r;
}

// Issue the async prefetch of one tile's x,y into buffer `dst`.
__device__ __forceinline__ void prefetch_tile(float* dst,
                                              const float4* __restrict__ X,
                                              const float4* __restrict__ Y,
                                              int tile, int tid)
{
    float* sx = dst;
    float* sy = dst + TILE * SXW;
    const int base4 = tile * TILE * 4;
#pragma unroll
    for (int it = 0; it < 4; ++it) {
        const int g = tid + it * TPB;        // float4 index within tile
        const int p = g >> 2, q = g & 3;
        cp16(smem_u32(sx + p * SXW + q * 4), X + base4 + g);
        cp16(smem_u32(sy + p * SXW + q * 4), Y + base4 + g);
    }
}

__global__ __launch_bounds__(TPB)
void MVGeometricBilinear_41274635715139_kernel(
    const float4* __restrict__ X,   // (n,16) floats = (n,4) float4
    const float4* __restrict__ Y,
    const float*  __restrict__ Rf,  // (n,16) floats; only element 15 used
    float4*       __restrict__ O,   // (n,32) floats = (n,8) float4
    int ntiles)
{
    __shared__ float sb[2 * BUFF];           // 40 KB static
    const int tid    = threadIdx.x;
    const int stride = gridDim.x;

    int tile   = blockIdx.x;
    int parity = 0;

    if (tile < ntiles)
        prefetch_tile(sb, X, Y, tile, tid);
    cp_commit();

    for (; tile < ntiles; tile += stride, parity ^= 1) {
        float* cb = sb + parity * BUFF;
        float* nb = sb + (parity ^ 1) * BUFF;

        // ref pseudoscalar for current tile: issue LDG early (hidden by wait).
        const float r = Rf[(tile * TILE + tid) * 16 + 15];

        const int nxt = tile + stride;
        if (nxt < ntiles) {
            prefetch_tile(nb, X, Y, nxt, tid);
            cp_commit();
            cp_wait<1>();                    // current tile's group landed
        } else {
            cp_commit();                     // empty group keeps counts aligned
            cp_wait<0>();
        }
        __syncthreads();                     // cb visible to all threads

        // Conflict-free per-thread reads (stride 20).
        float x[16], y[16];
        const float* sx = cb;
        const float* sy = cb + TILE * SXW;
#pragma unroll
        for (int q = 0; q < 4; ++q) {
            const float4 v = reinterpret_cast<const float4*>(sx + tid * SXW + q * 4)[0];
            x[4 * q + 0] = v.x; x[4 * q + 1] = v.y; x[4 * q + 2] = v.z; x[4 * q + 3] = v.w;
        }
#pragma unroll
        for (int q = 0; q < 4; ++q) {
            const float4 v = reinterpret_cast<const float4*>(sy + tid * SXW + q * 4)[0];
            y[4 * q + 0] = v.x; y[4 * q + 1] = v.y; y[4 * q + 2] = v.z; y[4 * q + 3] = v.w;
        }
        __syncthreads();                     // reads done before cb reused

        float gp[16], jn[16];
        mv_compute(x, y, r, gp, jn);

        // Stage outputs into cb (stride 36, conflict-free STS.128).
        float* so = cb;                      // 18 KB <= 20 KB buffer
#pragma unroll
        for (int q = 0; q < 4; ++q)
            reinterpret_cast<float4*>(so + tid * SOW + q * 4)[0] =
                make_float4(gp[4 * q], gp[4 * q + 1], gp[4 * q + 2], gp[4 * q + 3]);
#pragma unroll
        for (int q = 0; q < 4; ++q)
            reinterpret_cast<float4*>(so + tid * SOW + 16 + q * 4)[0] =
                make_float4(jn[4 * q], jn[4 * q + 1], jn[4 * q + 2], jn[4 * q + 3]);
        __syncthreads();                     // outputs visible for writeout

        // Fully coalesced STG.128 writeout.
        const int ob = tile * TILE * 8;
#pragma unroll
        for (int it = 0; it < 8; ++it) {
            const int g = tid + it * TPB;    // float4 index within out tile
            const int p = g >> 3, q = g & 7;
            O[ob + g] = reinterpret_cast<const float4*>(so + p * SOW + q * 4)[0];
        }
        __syncthreads();   // all smem reads done before next iter's cp.async
                           // overwrites cb (which is next iteration's nb)
    }
}

// Tail kernel (only if n % TILE != 0; not hit for this problem's shapes).
__global__ void MVGeometricBilinear_41274635715139_tail(
    const float4* __restrict__ X, const float4* __restrict__ Y,
    const float* __restrict__ Rf, float4* __restrict__ O, int n0, int n)
{
    const int t = n0 + blockIdx.x * blockDim.x + threadIdx.x;
    if (t >= n) return;
    float x[16], y[16];
#pragma unroll
    for (int q = 0; q < 4; q++) {
        const float4 v = X[t * 4 + q];
        x[4 * q + 0] = v.x; x[4 * q + 1] = v.y; x[4 * q + 2] = v.z; x[4 * q + 3] = v.w;
        const float4 w = Y[t * 4 + q];
        y[4 * q + 0] = w.x; y[4 * q + 1] = w.y; y[4 * q + 2] = w.z; y[4 * q + 3] = w.w;
    }
    const float r = Rf[t * 16 + 15];
    float gp[16], jn[16];
    mv_compute(x, y, r, gp, jn);
    float4* o = O + t * 8;
#pragma unroll
    for (int q = 0; q < 4; q++) {
        o[q]     = make_float4(gp[4 * q], gp[4 * q + 1], gp[4 * q + 2], gp[4 * q + 3]);
        o[4 + q] = make_float4(jn[4 * q], jn[4 * q + 1], jn[4 * q + 2], jn[4 * q + 3]);
    }
}

extern "C" void kernel_launch(void* const* d_in, const int* in_sizes, int n_in,
                              void* d_out, int out_size)
{
    const float4* x = (const float4*)d_in[0];
    const float4* y = (const float4*)d_in[1];
    const float*  r = (const float*)d_in[2];
    float4* o = (float4*)d_out;

    const int n      = in_sizes[0] / 16;    // number of multivector points
    const int ntiles = n / TILE;
    const int rem    = n - ntiles * TILE;

    if (ntiles > 0) {
        // 5 resident blocks/SM (40KB smem, 64 regs) x 148 SMs = 740.
        int grid = ntiles < 740 ? ntiles : 740;
        MVGeometricBilinear_41274635715139_kernel<<<grid, TPB>>>(x, y, r, o, ntiles);
    }
    if (rem > 0)
        MVGeometricBilinear_41274635715139_tail<<<(rem + 255) / 256, 256>>>(
            x, y, r, o, ntiles * TILE, n);
}

// round 9
// speedup vs baseline: 1.0626x; 1.0626x over previous
#include <cuda_runtime.h>
#include <cstdint>

// ---------------------------------------------------------------------------
// MVGeometricBilinear: PGA G(3,0,1) geometric product + equivariant join.
//   out[..., 0:16]  = x * y          (geometric product, e0^2 = 0)
//   out[..., 16:32] = ref_e0123 * dual(dual(x) ^ dual(y))
//
// Round 8: occupancy-focused rework of the cp.async pipeline.
//  - XOR-swizzled smem (no padding): 32KB/block -> 7 blocks/SM
//  - two-pass compute (gp then jn) to halve accumulator liveness, regs<=72
//  - grid = 152 SMs * 7 = 1064 for near-perfect persistent-loop balance
// Compute signs identical to the validated round-3..7 kernels.
// ---------------------------------------------------------------------------

__host__ __device__ constexpr int maskOf(int i) {
    constexpr int m[16] = {0, 1, 2, 4, 8, 3, 5, 9, 6, 10, 12, 7, 11, 13, 14, 15};
    return m[i];
}
__host__ __device__ constexpr int idxOfMask(int m) {
    constexpr int t[16] = {0, 1, 2, 5, 3, 6, 8, 11, 4, 7, 9, 12, 10, 13, 14, 15};
    return t[m];
}
__host__ __device__ constexpr int reorderSign(int a, int b) {
    int s = 0;
    for (int j = 0; j < 4; j++)
        if (b & (1 << j))
            for (int i = j + 1; i < 4; i++)
                if (a & (1 << i)) s++;
    return (s & 1) ? -1 : 1;
}
__host__ __device__ constexpr int gpSign(int i, int j) {
    const int a = maskOf(i), b = maskOf(j);
    if (a & b & 1) return 0;              // shared degenerate e0 -> vanishes
    return reorderSign(a, b);
}
__host__ __device__ constexpr int gpIdx(int i, int j) {
    return idxOfMask(maskOf(i) ^ maskOf(j));
}
__host__ __device__ constexpr int cIdx(int i) { return idxOfMask(15 ^ maskOf(i)); }
__host__ __device__ constexpr int cSign(int i) { return reorderSign(maskOf(i), 15 ^ maskOf(i)); }
__host__ __device__ constexpr int jSign(int i, int j) {
    const int a = maskOf(cIdx(i)), b = maskOf(cIdx(j));
    if (a & b) return 0;
    const int m = idxOfMask(a | b);
    return reorderSign(a, b) * cSign(i) * cSign(j) * cSign(m);
}
__host__ __device__ constexpr int jIdx(int i, int j) {
    const int a = maskOf(cIdx(i)), b = maskOf(cIdx(j));
    if (a & b) return 0;
    return cIdx(idxOfMask(a | b));
}

// ---------------------------------------------------------------------------

constexpr int TPB   = 128;              // threads per block
constexpr int TILE  = 128;              // points per tile (== TPB)
constexpr int INW   = TILE * 16;        // floats per input array per tile (2048)
constexpr int STAGE = INW * 2;          // x + y per stage = 4096 floats (16KB)
// total static smem: 2 stages = 8192 floats = 32KB -> 7 blocks/SM

// Swizzled word addresses (bank-conflict-free; verified per LDS/STS phase):
//   inputs : point p (0..127), float4-quarter q (0..3)
//   outputs: point p, float4-quarter qq (0..7)
__device__ __forceinline__ int in_word(int p, int q) {
    return (p << 4) + ((q ^ ((p >> 1) & 3)) << 2);
}
__device__ __forceinline__ int out_word(int p, int qq) {
    return (p << 5) + ((qq ^ (p & 7)) << 2);
}

__device__ __forceinline__ uint32_t smem_u32(const void* p) {
    return (uint32_t)__cvta_generic_to_shared(p);
}
__device__ __forceinline__ void cp16(uint32_t dst, const void* src) {
    asm volatile("cp.async.cg.shared.global [%0], [%1], 16;\n" :: "r"(dst), "l"(src));
}
__device__ __forceinline__ void cp_commit() {
    asm volatile("cp.async.commit_group;\n" ::: "memory");
}
template <int N> __device__ __forceinline__ void cp_wait() {
    asm volatile("cp.async.wait_group %0;\n" :: "n"(N) : "memory");
}

// Issue async prefetch of one tile's x,y into stage buffer `dst` (swizzled).
__device__ __forceinline__ void prefetch_tile(float* dst,
                                              const float4* __restrict__ X,
                                              const float4* __restrict__ Y,
                                              int tile, int tid)
{
    float* sx = dst;
    float* sy = dst + INW;
    const int base4 = tile * TILE * 4;
#pragma unroll
    for (int it = 0; it < 4; ++it) {
        const int g = tid + it * TPB;            // float4 index within tile
        const int p = g >> 2, q = g & 3;
        const int w = in_word(p, q);
        cp16(smem_u32(sx + w), X + base4 + g);
        cp16(smem_u32(sy + w), Y + base4 + g);
    }
}

__global__ __launch_bounds__(TPB, 7)
void MVGeometricBilinear_41274635715139_kernel(
    const float4* __restrict__ X,   // (n,16) floats = (n,4) float4
    const float4* __restrict__ Y,
    const float*  __restrict__ Rf,  // (n,16) floats; only element 15 used
    float4*       __restrict__ O,   // (n,32) floats = (n,8) float4
    int ntiles)
{
    __shared__ float sb[2 * STAGE];              // 32 KB static
    const int tid    = threadIdx.x;
    const int stride = gridDim.x;

    int tile   = blockIdx.x;
    int parity = 0;

    if (tile < ntiles)
        prefetch_tile(sb, X, Y, tile, tid);
    cp_commit();

    for (; tile < ntiles; tile += stride, parity ^= 1) {
        float* cb = sb + parity * STAGE;
        float* nb = sb + (parity ^ 1) * STAGE;

        // ref pseudoscalar for current tile (hidden under the wait below).
        const float r = Rf[(tile * TILE + tid) * 16 + 15];

        const int nxt = tile + stride;
        if (nxt < ntiles) {
            prefetch_tile(nb, X, Y, nxt, tid);
            cp_commit();
            cp_wait<1>();                        // current tile's group landed
        } else {
            cp_commit();                         // empty group keeps counts aligned
            cp_wait<0>();
        }
        __syncthreads();                         // cb visible to all threads

        // Conflict-free swizzled per-thread reads.
        float x[16], y[16];
        const float* sx = cb;
        const float* sy = cb + INW;
#pragma unroll
        for (int q = 0; q < 4; ++q) {
            const float4 v = reinterpret_cast<const float4*>(sx + in_word(tid, q))[0];
            x[4 * q + 0] = v.x; x[4 * q + 1] = v.y; x[4 * q + 2] = v.z; x[4 * q + 3] = v.w;
        }
#pragma unroll
        for (int q = 0; q < 4; ++q) {
            const float4 v = reinterpret_cast<const float4*>(sy + in_word(tid, q))[0];
            y[4 * q + 0] = v.x; y[4 * q + 1] = v.y; y[4 * q + 2] = v.z; y[4 * q + 3] = v.w;
        }
        __syncthreads();                         // all reads done before cb reused

        float* so = cb;                          // output staging (4096 floats)

        // ---- pass 1: geometric product (single 16-float accumulator) ------
        {
            float acc[16];
#pragma unroll
            for (int k = 0; k < 16; k++) acc[k] = 0.0f;
#pragma unroll
            for (int i = 0; i < 16; i++)
#pragma unroll
                for (int j = 0; j < 16; j++) {
                    const int s = gpSign(i, j);
                    const int k = gpIdx(i, j);
                    if (s == 1)       acc[k] += x[i] * y[j];
                    else if (s == -1) acc[k] -= x[i] * y[j];
                }
#pragma unroll
            for (int qq = 0; qq < 4; ++qq)
                reinterpret_cast<float4*>(so + out_word(tid, qq))[0] =
                    make_float4(acc[4 * qq], acc[4 * qq + 1],
                                acc[4 * qq + 2], acc[4 * qq + 3]);
        }

        // ---- pass 2: equivariant join (accumulator reused) ----------------
        {
            float acc[16];
#pragma unroll
            for (int k = 0; k < 16; k++) acc[k] = 0.0f;
#pragma unroll
            for (int i = 0; i < 16; i++)
#pragma unroll
                for (int j = 0; j < 16; j++) {
                    const int s = jSign(i, j);
                    const int k = jIdx(i, j);
                    if (s == 1)       acc[k] += x[i] * y[j];
                    else if (s == -1) acc[k] -= x[i] * y[j];
                }
#pragma unroll
            for (int qq = 0; qq < 4; ++qq)
                reinterpret_cast<float4*>(so + out_word(tid, qq + 4))[0] =
                    make_float4(r * acc[4 * qq], r * acc[4 * qq + 1],
                                r * acc[4 * qq + 2], r * acc[4 * qq + 3]);
        }
        __syncthreads();                         // outputs visible for writeout

        // Fully coalesced STG.128 writeout (swizzled smem readback).
        const int ob = tile * TILE * 8;
#pragma unroll
        for (int it = 0; it < 8; ++it) {
            const int g = tid + it * TPB;        // float4 index within out tile
            const int p = g >> 3, qq = g & 7;
            O[ob + g] = reinterpret_cast<const float4*>(so + out_word(p, qq))[0];
        }
        __syncthreads();   // all smem reads done before next iter's cp.async
                           // overwrites cb (next iteration's nb)
    }
}

// Tail kernel (only if n % TILE != 0; not hit for this problem's shapes).
__global__ void MVGeometricBilinear_41274635715139_tail(
    const float4* __restrict__ X, const float4* __restrict__ Y,
    const float* __restrict__ Rf, float4* __restrict__ O, int n0, int n)
{
    const int t = n0 + blockIdx.x * blockDim.x + threadIdx.x;
    if (t >= n) return;
    float x[16], y[16];
#pragma unroll
    for (int q = 0; q < 4; q++) {
        const float4 v = X[t * 4 + q];
        x[4 * q + 0] = v.x; x[4 * q + 1] = v.y; x[4 * q + 2] = v.z; x[4 * q + 3] = v.w;
        const float4 w = Y[t * 4 + q];
        y[4 * q + 0] = w.x; y[4 * q + 1] = w.y; y[4 * q + 2] = w.z; y[4 * q + 3] = w.w;
    }
    const float r = Rf[t * 16 + 15];
    float gp[16], jn[16];
#pragma unroll
    for (int k = 0; k < 16; k++) { gp[k] = 0.0f; jn[k] = 0.0f; }
#pragma unroll
    for (int i = 0; i < 16; i++)
#pragma unroll
        for (int j = 0; j < 16; j++) {
            { const int s = gpSign(i, j), k = gpIdx(i, j);
              if (s == 1) gp[k] += x[i] * y[j]; else if (s == -1) gp[k] -= x[i] * y[j]; }
            { const int s = jSign(i, j), k = jIdx(i, j);
              if (s == 1) jn[k] += x[i] * y[j]; else if (s == -1) jn[k] -= x[i] * y[j]; }
        }
    float4* o = O + t * 8;
#pragma unroll
    for (int q = 0; q < 4; q++) {
        o[q]     = make_float4(gp[4 * q], gp[4 * q + 1], gp[4 * q + 2], gp[4 * q + 3]);
        o[4 + q] = make_float4(r * jn[4 * q], r * jn[4 * q + 1],
                               r * jn[4 * q + 2], r * jn[4 * q + 3]);
    }
}

extern "C" void kernel_launch(void* const* d_in, const int* in_sizes, int n_in,
                              void* d_out, int out_size)
{
    const float4* x = (const float4*)d_in[0];
    const float4* y = (const float4*)d_in[1];
    const float*  r = (const float*)d_in[2];
    float4* o = (float4*)d_out;

    const int n      = in_sizes[0] / 16;    // number of multivector points
    const int ntiles = n / TILE;
    const int rem    = n - ntiles * TILE;

    if (ntiles > 0) {
        // 7 resident blocks/SM (32KB smem, <=72 regs) x 152 SMs = 1064.
        int grid = ntiles < 1064 ? ntiles : 1064;
        MVGeometricBilinear_41274635715139_kernel<<<grid, TPB>>>(x, y, r, o, ntiles);
    }
    if (rem > 0)
        MVGeometricBilinear_41274635715139_tail<<<(rem + 255) / 256, 256>>>(
            x, y, r, o, ntiles * TILE, n);
}

// round 11
// speedup vs baseline: 1.0748x; 1.0114x over previous
#include <cuda_runtime.h>
#include <cstdint>

// ---------------------------------------------------------------------------
// MVGeometricBilinear: PGA G(3,0,1) geometric product + equivariant join.
//   out[..., 0:16]  = x * y          (geometric product, e0^2 = 0)
//   out[..., 16:32] = ref_e0123 * dual(dual(x) ^ dual(y))
//
// Round 11 (resubmit of round 10; that bench died to container infra):
// small-tile high-residency pipeline.
//  - TILE=64, TPB=64: 17KB/block (incl. driver ovh) -> 13 blocks/SM resident
//  - all-resident balanced persistent grid (fixes round-9 queueing tail)
//  - 13 independent cp.async streams/SM smooth DRAM demand
// Compute signs identical to the validated round-3..9 kernels.
// ---------------------------------------------------------------------------

__host__ __device__ constexpr int maskOf(int i) {
    constexpr int m[16] = {0, 1, 2, 4, 8, 3, 5, 9, 6, 10, 12, 7, 11, 13, 14, 15};
    return m[i];
}
__host__ __device__ constexpr int idxOfMask(int m) {
    constexpr int t[16] = {0, 1, 2, 5, 3, 6, 8, 11, 4, 7, 9, 12, 10, 13, 14, 15};
    return t[m];
}
__host__ __device__ constexpr int reorderSign(int a, int b) {
    int s = 0;
    for (int j = 0; j < 4; j++)
        if (b & (1 << j))
            for (int i = j + 1; i < 4; i++)
                if (a & (1 << i)) s++;
    return (s & 1) ? -1 : 1;
}
__host__ __device__ constexpr int gpSign(int i, int j) {
    const int a = maskOf(i), b = maskOf(j);
    if (a & b & 1) return 0;              // shared degenerate e0 -> vanishes
    return reorderSign(a, b);
}
__host__ __device__ constexpr int gpIdx(int i, int j) {
    return idxOfMask(maskOf(i) ^ maskOf(j));
}
__host__ __device__ constexpr int cIdx(int i) { return idxOfMask(15 ^ maskOf(i)); }
__host__ __device__ constexpr int cSign(int i) { return reorderSign(maskOf(i), 15 ^ maskOf(i)); }
__host__ __device__ constexpr int jSign(int i, int j) {
    const int a = maskOf(cIdx(i)), b = maskOf(cIdx(j));
    if (a & b) return 0;
    const int m = idxOfMask(a | b);
    return reorderSign(a, b) * cSign(i) * cSign(j) * cSign(m);
}
__host__ __device__ constexpr int jIdx(int i, int j) {
    const int a = maskOf(cIdx(i)), b = maskOf(cIdx(j));
    if (a & b) return 0;
    return cIdx(idxOfMask(a | b));
}

// ---------------------------------------------------------------------------

constexpr int TPB   = 64;               // threads per block
constexpr int TILE  = 64;               // points per tile (== TPB)
constexpr int INW   = TILE * 16;        // floats per input array per tile (1024)
constexpr int STAGE = INW * 2;          // x + y per stage = 2048 floats (8KB)
// total static smem: 2 stages = 4096 floats = 16KB (+1KB ovh) -> 13 blocks/SM
constexpr int MAXBLK = 13;              // resident blocks per SM

// Swizzled word addresses (bank-conflict-free for every LDS.128/STS.128 phase;
// pattern depends only on (p mod 8, q), unchanged from round 8):
//   inputs : point p, float4-quarter q (0..3)
//   outputs: point p, float4-quarter qq (0..7)
__device__ __forceinline__ int in_word(int p, int q) {
    return (p << 4) + ((q ^ ((p >> 1) & 3)) << 2);
}
__device__ __forceinline__ int out_word(int p, int qq) {
    return (p << 5) + ((qq ^ (p & 7)) << 2);
}

__device__ __forceinline__ uint32_t smem_u32(const void* p) {
    return (uint32_t)__cvta_generic_to_shared(p);
}
__device__ __forceinline__ void cp16(uint32_t dst, const void* src) {
    asm volatile("cp.async.cg.shared.global [%0], [%1], 16;\n" :: "r"(dst), "l"(src));
}
__device__ __forceinline__ void cp_commit() {
    asm volatile("cp.async.commit_group;\n" ::: "memory");
}
template <int N> __device__ __forceinline__ void cp_wait() {
    asm volatile("cp.async.wait_group %0;\n" :: "n"(N) : "memory");
}

// Issue async prefetch of one tile's x,y into stage buffer `dst` (swizzled).
__device__ __forceinline__ void prefetch_tile(float* dst,
                                              const float4* __restrict__ X,
                                              const float4* __restrict__ Y,
                                              int tile, int tid)
{
    float* sx = dst;
    float* sy = dst + INW;
    const int base4 = tile * TILE * 4;
#pragma unroll
    for (int it = 0; it < 4; ++it) {
        const int g = tid + it * TPB;            // float4 index within tile
        const int p = g >> 2, q = g & 3;
        const int w = in_word(p, q);
        cp16(smem_u32(sx + w), X + base4 + g);
        cp16(smem_u32(sy + w), Y + base4 + g);
    }
}

__global__ __launch_bounds__(TPB, MAXBLK)
void MVGeometricBilinear_41274635715139_kernel(
    const float4* __restrict__ X,   // (n,16) floats = (n,4) float4
    const float4* __restrict__ Y,
    const float*  __restrict__ Rf,  // (n,16) floats; only element 15 used
    float4*       __restrict__ O,   // (n,32) floats = (n,8) float4
    int ntiles)
{
    __shared__ float sb[2 * STAGE];              // 16 KB static
    const int tid    = threadIdx.x;
    const int stride = gridDim.x;

    int tile   = blockIdx.x;
    int parity = 0;

    if (tile < ntiles)
        prefetch_tile(sb, X, Y, tile, tid);
    cp_commit();

    for (; tile < ntiles; tile += stride, parity ^= 1) {
        float* cb = sb + parity * STAGE;
        float* nb = sb + (parity ^ 1) * STAGE;

        // ref pseudoscalar for current tile (hidden under the wait below).
        const float r = Rf[(tile * TILE + tid) * 16 + 15];

        const int nxt = tile + stride;
        if (nxt < ntiles) {
            prefetch_tile(nb, X, Y, nxt, tid);
            cp_commit();
            cp_wait<1>();                        // current tile's group landed
        } else {
            cp_commit();                         // empty group keeps counts aligned
            cp_wait<0>();
        }
        __syncthreads();                         // cb visible to all threads

        // Conflict-free swizzled per-thread reads.
        float x[16], y[16];
        const float* sx = cb;
        const float* sy = cb + INW;
#pragma unroll
        for (int q = 0; q < 4; ++q) {
            const float4 v = reinterpret_cast<const float4*>(sx + in_word(tid, q))[0];
            x[4 * q + 0] = v.x; x[4 * q + 1] = v.y; x[4 * q + 2] = v.z; x[4 * q + 3] = v.w;
        }
#pragma unroll
        for (int q = 0; q < 4; ++q) {
            const float4 v = reinterpret_cast<const float4*>(sy + in_word(tid, q))[0];
            y[4 * q + 0] = v.x; y[4 * q + 1] = v.y; y[4 * q + 2] = v.z; y[4 * q + 3] = v.w;
        }
        __syncthreads();                         // all reads done before cb reused

        float* so = cb;                          // output staging (2048 floats)

        // ---- pass 1: geometric product (single 16-float accumulator) ------
        {
            float acc[16];
#pragma unroll
            for (int k = 0; k < 16; k++) acc[k] = 0.0f;
#pragma unroll
            for (int i = 0; i < 16; i++)
#pragma unroll
                for (int j = 0; j < 16; j++) {
                    const int s = gpSign(i, j);
                    const int k = gpIdx(i, j);
                    if (s == 1)       acc[k] += x[i] * y[j];
                    else if (s == -1) acc[k] -= x[i] * y[j];
                }
#pragma unroll
            for (int qq = 0; qq < 4; ++qq)
                reinterpret_cast<float4*>(so + out_word(tid, qq))[0] =
                    make_float4(acc[4 * qq], acc[4 * qq + 1],
                                acc[4 * qq + 2], acc[4 * qq + 3]);
        }

        // ---- pass 2: equivariant join (accumulator reused) ----------------
        {
            float acc[16];
#pragma unroll
            for (int k = 0; k < 16; k++) acc[k] = 0.0f;
#pragma unroll
            for (int i = 0; i < 16; i++)
#pragma unroll
                for (int j = 0; j < 16; j++) {
                    const int s = jSign(i, j);
                    const int k = jIdx(i, j);
                    if (s == 1)       acc[k] += x[i] * y[j];
                    else if (s == -1) acc[k] -= x[i] * y[j];
                }
#pragma unroll
            for (int qq = 0; qq < 4; ++qq)
                reinterpret_cast<float4*>(so + out_word(tid, qq + 4))[0] =
                    make_float4(r * acc[4 * qq], r * acc[4 * qq + 1],
                                r * acc[4 * qq + 2], r * acc[4 * qq + 3]);
        }
        __syncthreads();                         // outputs visible for writeout

        // Fully coalesced STG.128 writeout (swizzled smem readback).
        const int ob = tile * TILE * 8;
#pragma unroll
        for (int it = 0; it < 8; ++it) {
            const int g = tid + it * TPB;        // float4 index within out tile
            const int p = g >> 3, qq = g & 7;
            O[ob + g] = reinterpret_cast<const float4*>(so + out_word(p, qq))[0];
        }
        __syncthreads();   // all smem reads done before next iter's cp.async
                           // overwrites cb (next iteration's nb)
    }
}

// Tail kernel (only if n % TILE != 0; n = 524288 is divisible by 64).
__global__ void MVGeometricBilinear_41274635715139_tail(
    const float4* __restrict__ X, const float4* __restrict__ Y,
    const float* __restrict__ Rf, float4* __restrict__ O, int n0, int n)
{
    const int t = n0 + blockIdx.x * blockDim.x + threadIdx.x;
    if (t >= n) return;
    float x[16], y[16];
#pragma unroll
    for (int q = 0; q < 4; q++) {
        const float4 v = X[t * 4 + q];
        x[4 * q + 0] = v.x; x[4 * q + 1] = v.y; x[4 * q + 2] = v.z; x[4 * q + 3] = v.w;
        const float4 w = Y[t * 4 + q];
        y[4 * q + 0] = w.x; y[4 * q + 1] = w.y; y[4 * q + 2] = w.z; y[4 * q + 3] = w.w;
    }
    const float r = Rf[t * 16 + 15];
    float gp[16], jn[16];
#pragma unroll
    for (int k = 0; k < 16; k++) { gp[k] = 0.0f; jn[k] = 0.0f; }
#pragma unroll
    for (int i = 0; i < 16; i++)
#pragma unroll
        for (int j = 0; j < 16; j++) {
            { const int s = gpSign(i, j), k = gpIdx(i, j);
              if (s == 1) gp[k] += x[i] * y[j]; else if (s == -1) gp[k] -= x[i] * y[j]; }
            { const int s = jSign(i, j), k = jIdx(i, j);
              if (s == 1) jn[k] += x[i] * y[j]; else if (s == -1) jn[k] -= x[i] * y[j]; }
        }
    float4* o = O + t * 8;
#pragma unroll
    for (int q = 0; q < 4; q++) {
        o[q]     = make_float4(gp[4 * q], gp[4 * q + 1], gp[4 * q + 2], gp[4 * q + 3]);
        o[4 + q] = make_float4(r * jn[4 * q], r * jn[4 * q + 1],
                               r * jn[4 * q + 2], r * jn[4 * q + 3]);
    }
}

extern "C" void kernel_launch(void* const* d_in, const int* in_sizes, int n_in,
                              void* d_out, int out_size)
{
    const float4* x = (const float4*)d_in[0];
    const float4* y = (const float4*)d_in[1];
    const float*  r = (const float*)d_in[2];
    float4* o = (float4*)d_out;

    const int n      = in_sizes[0] / 16;    // number of multivector points
    const int ntiles = n / TILE;
    const int rem    = n - ntiles * TILE;

    if (ntiles > 0) {
        // All-resident, balanced persistent grid:
        // capacity = 13 blocks/SM * 152 SMs = 1976.
        // grid = ceil(ntiles / ceil(ntiles / capacity)) keeps every block
        // resident with an even 5/4-tile split (ntiles=8192 -> grid=1639).
        const int capacity = MAXBLK * 152;
        int grid;
        if (ntiles <= capacity) {
            grid = ntiles;
        } else {
            const int rounds = (ntiles + capacity - 1) / capacity;
            grid = (ntiles + rounds - 1) / rounds;
        }
        MVGeometricBilinear_41274635715139_kernel<<<grid, TPB>>>(x, y, r, o, ntiles);
    }
    if (rem > 0)
        MVGeometricBilinear_41274635715139_tail<<<(rem + 255) / 256, 256>>>(
            x, y, r, o, ntiles * TILE, n);
}